// round 10
// baseline (speedup 1.0000x reference)
#include <cuda_runtime.h>
#include <cuda_bf16.h>
#include <cuda_fp16.h>
#include <math.h>
#include <stdint.h>

#define N_NODES 100000
#define N_EDGES 3200000
#define F_IN    512
#define HID     256
#define NCLS    64
#define NLAYERS 8
#define ALPHA   0.1f
#define NBLK    ((N_NODES + 63) / 64)   // 1563

// ---------------- device scratch (static, no allocations) ----------------
__device__ __half g_hfA[(size_t)N_NODES * HID];          // h ping (fp16, scaled 16^-l)
__device__ __half g_hfB[(size_t)N_NODES * HID];          // h pong (fp16, scaled)
__device__ float g_x0[(size_t)N_NODES * HID];
__device__ __nv_bfloat16 g_mhi[(size_t)N_NODES * HID];   // last-layer h hi (true scale)
__device__ __nv_bfloat16 g_mlo[(size_t)N_NODES * HID];   // last-layer h lo
__device__ __nv_bfloat16 g_xhi[(size_t)N_NODES * F_IN];
__device__ __nv_bfloat16 g_xlo[(size_t)N_NODES * F_IN];
__device__ __nv_bfloat16 g_Winhi[HID * F_IN];            // [n][k]
__device__ __nv_bfloat16 g_Winlo[HID * F_IN];
__device__ __nv_bfloat16 g_Wlhi[NLAYERS * HID * HID];    // [l][n][k]
__device__ __nv_bfloat16 g_Wllo[NLAYERS * HID * HID];
__device__ __nv_bfloat16 g_Wouthi[NCLS * HID];           // [n][k]
__device__ __nv_bfloat16 g_Woutlo[NCLS * HID];
__device__ int   g_rowptr[N_NODES + 1];
__device__ int   g_cnt[N_NODES];
__device__ int   g_colv[N_EDGES];
__device__ float g_valv[N_EDGES];

// ---------------- PTX helpers (arch-agnostic: sm_80+) ----------------
__device__ __forceinline__ uint32_t smem_u32(const void* p) {
    uint32_t a;
    asm("{ .reg .u64 t; cvta.to.shared.u64 t, %1; cvt.u32.u64 %0, t; }" : "=r"(a) : "l"(p));
    return a;
}
__device__ __forceinline__ void cp_async16(uint32_t dst, const void* src) {
    asm volatile("cp.async.cg.shared.global [%0], [%1], 16;" :: "r"(dst), "l"(src));
}
#define CP_COMMIT() asm volatile("cp.async.commit_group;" ::: "memory")
#define CP_WAIT0()  asm volatile("cp.async.wait_group 0;" ::: "memory")
#define BAR_SYNC(id, cnt)   asm volatile("bar.sync %0, %1;"   :: "r"(id), "r"(cnt) : "memory")
#define BAR_ARRIVE(id, cnt) asm volatile("bar.arrive %0, %1;" :: "r"(id), "r"(cnt) : "memory")

__device__ __forceinline__ void ldmx4(uint32_t* r, uint32_t addr) {
    asm volatile("ldmatrix.sync.aligned.m8n8.x4.shared.b16 {%0,%1,%2,%3}, [%4];"
                 : "=r"(r[0]), "=r"(r[1]), "=r"(r[2]), "=r"(r[3]) : "r"(addr));
}
__device__ __forceinline__ void ldmx2(uint32_t* r, uint32_t addr) {
    asm volatile("ldmatrix.sync.aligned.m8n8.x2.shared.b16 {%0,%1}, [%2];"
                 : "=r"(r[0]), "=r"(r[1]) : "r"(addr));
}
__device__ __forceinline__ void mma16816(float* d, const uint32_t* a, const uint32_t* b) {
    asm volatile("mma.sync.aligned.m16n8k16.row.col.f32.bf16.bf16.f32 "
                 "{%0,%1,%2,%3}, {%4,%5,%6,%7}, {%8,%9}, {%0,%1,%2,%3};"
                 : "+f"(d[0]), "+f"(d[1]), "+f"(d[2]), "+f"(d[3])
                 : "r"(a[0]), "r"(a[1]), "r"(a[2]), "r"(a[3]), "r"(b[0]), "r"(b[1]));
}

// ---------------- CSR build ----------------
__global__ void zero_cnt_kernel() {
    int i = blockIdx.x * blockDim.x + threadIdx.x;
    if (i < N_NODES) g_cnt[i] = 0;
}
__global__ void count_kernel(const int* __restrict__ edge_row) {
    int e = blockIdx.x * blockDim.x + threadIdx.x;
    if (e < N_EDGES) atomicAdd(&g_cnt[edge_row[e]], 1);
}
__global__ void scan_kernel() {
    __shared__ int s[1024];
    const int t = threadIdx.x;
    const int CH = (N_NODES + 1023) / 1024;
    int begin = t * CH;
    int end = begin + CH; if (end > N_NODES) end = N_NODES;
    if (begin > N_NODES) begin = N_NODES;
    int sum = 0;
    for (int i = begin; i < end; i++) sum += g_cnt[i];
    s[t] = sum;
    __syncthreads();
    for (int off = 1; off < 1024; off <<= 1) {
        int v = (t >= off) ? s[t - off] : 0;
        __syncthreads();
        s[t] += v;
        __syncthreads();
    }
    int run = s[t] - sum;
    for (int i = begin; i < end; i++) {
        int c = g_cnt[i];
        g_rowptr[i] = run;
        run += c;
        g_cnt[i] = 0;
    }
    if (t == 1023) g_rowptr[N_NODES] = s[1023];
}
__global__ void scatter_kernel(const int* __restrict__ edge_row,
                               const int* __restrict__ edge_col,
                               const float* __restrict__ edge_val) {
    int e = blockIdx.x * blockDim.x + threadIdx.x;
    if (e < N_EDGES) {
        int r = edge_row[e];
        int pos = g_rowptr[r] + atomicAdd(&g_cnt[r], 1);
        g_colv[pos] = edge_col[e];
        g_valv[pos] = edge_val[e];
    }
}

// ---------------- conversions ----------------
__device__ __forceinline__ void split_bf16(float v, __nv_bfloat16& hi, __nv_bfloat16& lo) {
    hi = __float2bfloat16_rn(v);
    lo = __float2bfloat16_rn(v - __bfloat162float(hi));
}

__global__ void split_x_kernel(const float* __restrict__ x) {
    size_t i = (size_t)blockIdx.x * blockDim.x + threadIdx.x;
    size_t total = (size_t)N_NODES * F_IN / 4;
    if (i >= total) return;
    float4 v = ((const float4*)x)[i];
    __nv_bfloat16 h0, h1, h2, h3, l0, l1, l2, l3;
    split_bf16(v.x, h0, l0); split_bf16(v.y, h1, l1);
    split_bf16(v.z, h2, l2); split_bf16(v.w, h3, l3);
    __nv_bfloat162 ph0 = __halves2bfloat162(h0, h1), ph1 = __halves2bfloat162(h2, h3);
    __nv_bfloat162 pl0 = __halves2bfloat162(l0, l1), pl1 = __halves2bfloat162(l2, l3);
    ((uint2*)g_xhi)[i] = make_uint2(*(uint32_t*)&ph0, *(uint32_t*)&ph1);
    ((uint2*)g_xlo)[i] = make_uint2(*(uint32_t*)&pl0, *(uint32_t*)&pl1);
}

__global__ void conv_weights_kernel(const float* __restrict__ W_in,
                                    const float* __restrict__ conv_W,
                                    const float* __restrict__ W_out) {
    int i = blockIdx.x * blockDim.x + threadIdx.x;
    const int NIN = HID * F_IN;
    const int NL = NLAYERS * HID * HID;
    if (i < NIN) {
        int n = i / F_IN, k = i % F_IN;
        __nv_bfloat16 hi, lo;
        split_bf16(W_in[(size_t)k * HID + n], hi, lo);
        g_Winhi[i] = hi; g_Winlo[i] = lo;
    } else if (i < NIN + NL) {
        int j = i - NIN;
        int l = j / (HID * HID);
        int r = j % (HID * HID);
        int n = r / HID, k = r % HID;
        __nv_bfloat16 hi, lo;
        split_bf16(conv_W[(size_t)l * HID * HID + (size_t)k * HID + n], hi, lo);
        g_Wlhi[j] = hi; g_Wllo[j] = lo;
    } else {
        int j = i - NIN - NL;
        if (j < NCLS * HID) {
            int n = j / HID, k = j % HID;
            __nv_bfloat16 hi, lo;
            split_bf16(W_out[(size_t)k * NCLS + n], hi, lo);
            g_Wouthi[j] = hi; g_Woutlo[j] = lo;
        }
    }
}

// ============ warp-specialized fused layer ============
// 1 CTA/SM persistent. Warps 0-7 = producers: gather + mix + bf16-split into a
// 2-slot SMEM A-ring. Warps 8-15 = consumers: bf16x3 MMA GEMM + epilogue.
// Named barriers: full[s] = 1+s (prod arrive / cons sync, 512);
//                 empty[s] = 3+s (cons arrive / prod sync, 512);
//                 consumer-internal W pipeline = 5 (256).
#define FBM 64
#define AST 264                          // bf16 per A smem row (528B, ldmatrix conflict-free)
#define A_ELEMS (FBM * AST)              // 16896 elems per matrix
#define SLOT_ELEMS (2 * A_ELEMS)         // hi+lo per slot
#define WSTRIDE 40
#define W_ELEMS (64 * WSTRIDE)           // 2560 elems per matrix per stage
#define WB_E (2 * SLOT_ELEMS)            // 67584 elem offset of W region
#define FUSED_SMEM ((WB_E + 2 * 2 * W_ELEMS) * 2)   // 155648 bytes

__device__ __forceinline__ void acc_half8(float4& a, float4& b, float v, const uint4& u) {
    const __half2* p = (const __half2*)&u;
    float2 f0 = __half22float2(p[0]);
    float2 f1 = __half22float2(p[1]);
    float2 f2 = __half22float2(p[2]);
    float2 f3 = __half22float2(p[3]);
    a.x += v * f0.x; a.y += v * f0.y; a.z += v * f1.x; a.w += v * f1.y;
    b.x += v * f2.x; b.y += v * f2.y; b.z += v * f3.x; b.w += v * f3.y;
}

__global__ void __launch_bounds__(512, 1)
fused_layer_kernel(const __half* __restrict__ h_in, __half* __restrict__ h_out,
                   const __nv_bfloat16* __restrict__ Whi,
                   const __nv_bfloat16* __restrict__ Wlo,
                   float beta, float unscale, float scale_out, int last) {
    extern __shared__ __nv_bfloat16 sm[];
    const uint32_t smb = smem_u32(sm);
    const int tid = threadIdx.x;
    const int wid = tid >> 5, lane = tid & 31;
    const float wmix = 1.f - beta;

    if (tid < 256) {
        // ======================= PRODUCER =======================
        const uint4* hp = (const uint4*)h_in;
        const float ua = (1.f - ALPHA) * unscale;
        int i = 0;
        for (int b = blockIdx.x; b < NBLK; b += gridDim.x, i++) {
            const int slot = i & 1;
            if (i >= 2) BAR_SYNC(3 + slot, 512);
            __nv_bfloat16* Ah = sm + slot * SLOT_ELEMS;
            __nv_bfloat16* Al = Ah + A_ELEMS;
            const int row0 = b * FBM;
#pragma unroll
            for (int it = 0; it < 8; it++) {
                const int rl = it * 8 + wid;
                const int row = row0 + rl;
                float4 a = make_float4(0.f, 0.f, 0.f, 0.f);
                float4 bb = make_float4(0.f, 0.f, 0.f, 0.f);
                float4 ma = a, mb = bb;
                if (row < N_NODES) {
                    const int start = g_rowptr[row];
                    const int end = g_rowptr[row + 1];
                    int e = start;
                    for (; e + 7 < end; e += 8) {
                        int cc[8]; float vv[8]; uint4 uu[8];
#pragma unroll
                        for (int j = 0; j < 8; j++) { cc[j] = g_colv[e + j]; vv[j] = g_valv[e + j]; }
#pragma unroll
                        for (int j = 0; j < 8; j++) uu[j] = hp[(size_t)cc[j] * 32 + lane];
#pragma unroll
                        for (int j = 0; j < 8; j++) acc_half8(a, bb, vv[j], uu[j]);
                    }
                    for (; e < end; e++) {
                        int c0 = g_colv[e];
                        float v0 = g_valv[e];
                        uint4 u0 = hp[(size_t)c0 * 32 + lane];
                        acc_half8(a, bb, v0, u0);
                    }
                    float4 xa = ((const float4*)g_x0)[(size_t)row * 64 + lane * 2];
                    float4 xb = ((const float4*)g_x0)[(size_t)row * 64 + lane * 2 + 1];
                    ma.x = ua * a.x + ALPHA * xa.x;
                    ma.y = ua * a.y + ALPHA * xa.y;
                    ma.z = ua * a.z + ALPHA * xa.z;
                    ma.w = ua * a.w + ALPHA * xa.w;
                    mb.x = ua * bb.x + ALPHA * xb.x;
                    mb.y = ua * bb.y + ALPHA * xb.y;
                    mb.z = ua * bb.z + ALPHA * xb.z;
                    mb.w = ua * bb.w + ALPHA * xb.w;
                }
                __nv_bfloat16 h0, h1, h2, h3, h4, h5, h6, h7;
                __nv_bfloat16 l0, l1, l2, l3, l4, l5, l6, l7;
                split_bf16(ma.x, h0, l0); split_bf16(ma.y, h1, l1);
                split_bf16(ma.z, h2, l2); split_bf16(ma.w, h3, l3);
                split_bf16(mb.x, h4, l4); split_bf16(mb.y, h5, l5);
                split_bf16(mb.z, h6, l6); split_bf16(mb.w, h7, l7);
                __nv_bfloat162 ph0 = __halves2bfloat162(h0, h1), ph1 = __halves2bfloat162(h2, h3);
                __nv_bfloat162 ph2 = __halves2bfloat162(h4, h5), ph3 = __halves2bfloat162(h6, h7);
                __nv_bfloat162 pl0 = __halves2bfloat162(l0, l1), pl1 = __halves2bfloat162(l2, l3);
                __nv_bfloat162 pl2 = __halves2bfloat162(l4, l5), pl3 = __halves2bfloat162(l6, l7);
                *(uint4*)(Ah + rl * AST + lane * 8) =
                    make_uint4(*(uint32_t*)&ph0, *(uint32_t*)&ph1, *(uint32_t*)&ph2, *(uint32_t*)&ph3);
                *(uint4*)(Al + rl * AST + lane * 8) =
                    make_uint4(*(uint32_t*)&pl0, *(uint32_t*)&pl1, *(uint32_t*)&pl2, *(uint32_t*)&pl3);
            }
            __threadfence_block();
            BAR_ARRIVE(1 + slot, 512);
        }
    } else {
        // ======================= CONSUMER =======================
        const int cw = wid - 8;          // 0..7
        const int wm = cw >> 2;          // 0..1 : 32-row half
        const int wn = cw & 3;           // 0..3 : 16-col tile within 64
        const int ctid = tid - 256;      // 0..255

        int i = 0;
        for (int b = blockIdx.x; b < NBLK; b += gridDim.x, i++) {
            const int slot = i & 1;
            BAR_SYNC(1 + slot, 512);     // wait full
            const uint32_t abase = smb + (uint32_t)(slot * SLOT_ELEMS) * 2;
            const __nv_bfloat16* Ah = sm + slot * SLOT_ELEMS;
            const __nv_bfloat16* Al = Ah + A_ELEMS;
            const int row0 = b * FBM;

            for (int nt4 = 0; nt4 < 4; nt4++) {
                float acc[2][2][4];
#pragma unroll
                for (int p = 0; p < 2; p++)
#pragma unroll
                    for (int q = 0; q < 2; q++)
#pragma unroll
                        for (int f = 0; f < 4; f++) acc[p][q][f] = 0.f;

                // W chunk loader (consumer threads only)
                auto load_w = [&](int c, int s) {
                    int r = ctid >> 2, v = ctid & 3;
                    size_t soff = (size_t)(nt4 * 64 + r) * HID + c * 32 + v * 8;
                    uint32_t off = WB_E + s * (2 * W_ELEMS) + r * WSTRIDE + v * 8;
                    cp_async16(smb + off * 2, Whi + soff);
                    cp_async16(smb + (off + W_ELEMS) * 2, Wlo + soff);
                };

                load_w(0, 0);
                CP_COMMIT();
                for (int c = 0; c < 8; c++) {
                    CP_WAIT0();
                    BAR_SYNC(5, 256);
                    if (c + 1 < 8) { load_w(c + 1, (c + 1) & 1); CP_COMMIT(); }
                    const uint32_t wsb = smb + (uint32_t)(WB_E + (c & 1) * (2 * W_ELEMS)) * 2;
#pragma unroll
                    for (int ks = 0; ks < 2; ks++) {
                        uint32_t ah[2][4], al[2][4], bh[2][2], bl[2][2];
#pragma unroll
                        for (int mt = 0; mt < 2; mt++) {
                            uint32_t aAddr = abase + (uint32_t)((wm * 32 + mt * 16 + (lane & 15)) * AST
                                           + c * 32 + ks * 16 + (lane >> 4) * 8) * 2;
                            ldmx4(ah[mt], aAddr);
                            ldmx4(al[mt], aAddr + A_ELEMS * 2);
                        }
#pragma unroll
                        for (int nt = 0; nt < 2; nt++) {
                            uint32_t bAddr = wsb + (uint32_t)((wn * 16 + nt * 8 + (lane & 7)) * WSTRIDE
                                           + ks * 16 + ((lane >> 3) & 1) * 8) * 2;
                            ldmx2(bh[nt], bAddr);
                            ldmx2(bl[nt], bAddr + W_ELEMS * 2);
                        }
#pragma unroll
                        for (int mt = 0; mt < 2; mt++)
#pragma unroll
                            for (int nt = 0; nt < 2; nt++) {
                                mma16816(acc[mt][nt], ah[mt], bh[nt]);
                                mma16816(acc[mt][nt], ah[mt], bl[nt]);
                                mma16816(acc[mt][nt], al[mt], bh[nt]);
                            }
                    }
                    BAR_SYNC(5, 256);
                }

                // epilogue for this 64-col tile
#pragma unroll
                for (int mt = 0; mt < 2; mt++)
#pragma unroll
                    for (int half = 0; half < 2; half++) {
                        int rl = wm * 32 + mt * 16 + half * 8 + (lane >> 2);
                        int grow = row0 + rl;
                        if (grow >= N_NODES) continue;
#pragma unroll
                        for (int nt = 0; nt < 2; nt++) {
                            int gc = nt4 * 64 + wn * 16 + nt * 8 + (lane & 3) * 2;
                            uint32_t hiw = *(uint32_t*)(Ah + rl * AST + gc);
                            uint32_t low = *(uint32_t*)(Al + rl * AST + gc);
                            __nv_bfloat162 hv = *(__nv_bfloat162*)&hiw;
                            __nv_bfloat162 lv = *(__nv_bfloat162*)&low;
                            float m0 = __bfloat162float(hv.x) + __bfloat162float(lv.x);
                            float m1 = __bfloat162float(hv.y) + __bfloat162float(lv.y);
                            float v0 = fmaxf(wmix * m0 + beta * acc[mt][nt][half * 2 + 0], 0.f);
                            float v1 = fmaxf(wmix * m1 + beta * acc[mt][nt][half * 2 + 1], 0.f);
                            if (!last) {
                                __half2 o = __floats2half2_rn(v0 * scale_out, v1 * scale_out);
                                *(uint32_t*)&h_out[(size_t)grow * HID + gc] = *(uint32_t*)&o;
                            } else {
                                __nv_bfloat16 hh0, hl0, hh1, hl1;
                                split_bf16(v0, hh0, hl0);
                                split_bf16(v1, hh1, hl1);
                                __nv_bfloat162 ph = __halves2bfloat162(hh0, hh1);
                                __nv_bfloat162 pl = __halves2bfloat162(hl0, hl1);
                                *(uint32_t*)&g_mhi[(size_t)grow * HID + gc] = *(uint32_t*)&ph;
                                *(uint32_t*)&g_mlo[(size_t)grow * HID + gc] = *(uint32_t*)&pl;
                            }
                        }
                    }
            }
            BAR_ARRIVE(3 + slot, 512);   // mark empty
        }
    }
}

// ---------------- bf16x3 MMA GEMM (input + output layers) ----------------
#define BM 128
#define BN 64
#define BKC 32
#define ASTRIDE 40
#define A_STG (BM * ASTRIDE)
#define B_STG (BN * ASTRIDE)
#define STG_ELEMS (2 * A_STG + 2 * B_STG)
#define GEMM_SMEM (2 * STG_ELEMS * 2)

__global__ void __launch_bounds__(256, 2)
mma_gemm_kernel(const __nv_bfloat16* __restrict__ Ahi, const __nv_bfloat16* __restrict__ Alo,
                int lda, int chunks,
                const __nv_bfloat16* __restrict__ Bhi, const __nv_bfloat16* __restrict__ Blo,
                const float* __restrict__ bias,
                float* __restrict__ outf, __half* __restrict__ outh,
                int ldc, int do_relu) {
    extern __shared__ __nv_bfloat16 smg[];
    const uint32_t smb = smem_u32(smg);
    const int tid = threadIdx.x;
    const int row0 = blockIdx.y * BM;
    const int n0 = blockIdx.x * BN;
    const int wid = tid >> 5, lane = tid & 31;
    const int wm = wid >> 1, wn = wid & 1;

    auto load_chunk = [&](int c, int s) {
        const int base = s * STG_ELEMS;
        const __nv_bfloat16* ah = Ahi + (size_t)c * BKC;
        const __nv_bfloat16* al = Alo + (size_t)c * BKC;
#pragma unroll
        for (int i = 0; i < 2; i++) {
            int idx = tid + i * 256;
            int r = idx >> 2, v = idx & 3;
            int rg = row0 + r; if (rg >= N_NODES) rg = N_NODES - 1;
            uint32_t d = smb + (uint32_t)(base + r * ASTRIDE + v * 8) * 2;
            cp_async16(d, ah + (size_t)rg * lda + v * 8);
            cp_async16(d + A_STG * 2, al + (size_t)rg * lda + v * 8);
        }
        {
            int r = tid >> 2, v = tid & 3;
            uint32_t d = smb + (uint32_t)(base + 2 * A_STG + r * ASTRIDE + v * 8) * 2;
            size_t off = (size_t)(n0 + r) * lda + (size_t)c * BKC + v * 8;
            cp_async16(d, Bhi + off);
            cp_async16(d + B_STG * 2, Blo + off);
        }
    };

    float acc[2][4][4];
#pragma unroll
    for (int i = 0; i < 2; i++)
#pragma unroll
        for (int j = 0; j < 4; j++)
#pragma unroll
            for (int k = 0; k < 4; k++) acc[i][j][k] = 0.f;

    load_chunk(0, 0);
    CP_COMMIT();

    for (int c = 0; c < chunks; c++) {
        CP_WAIT0();
        __syncthreads();
        if (c + 1 < chunks) {
            load_chunk(c + 1, (c + 1) & 1);
            CP_COMMIT();
        }
        const int base = (c & 1) * STG_ELEMS;
        uint32_t aAddr = smb + (uint32_t)(base + (wm * 32 + (lane & 15)) * ASTRIDE + (lane >> 4) * 8) * 2;
        uint32_t bAddr = smb + (uint32_t)(base + 2 * A_STG + (wn * 32 + (lane & 7)) * ASTRIDE + ((lane >> 3) & 1) * 8) * 2;
#pragma unroll
        for (int ks = 0; ks < 2; ks++) {
            uint32_t ah[2][4], al[2][4], bh[4][2], bl[4][2];
#pragma unroll
            for (int mt = 0; mt < 2; mt++) {
                uint32_t addr = aAddr + (uint32_t)mt * (16 * ASTRIDE * 2) + ks * 32;
                ldmx4(ah[mt], addr);
                ldmx4(al[mt], addr + A_STG * 2);
            }
#pragma unroll
            for (int nt = 0; nt < 4; nt++) {
                uint32_t addr = bAddr + (uint32_t)nt * (8 * ASTRIDE * 2) + ks * 32;
                ldmx2(bh[nt], addr);
                ldmx2(bl[nt], addr + B_STG * 2);
            }
#pragma unroll
            for (int mt = 0; mt < 2; mt++)
#pragma unroll
                for (int nt = 0; nt < 4; nt++) {
                    mma16816(acc[mt][nt], ah[mt], bh[nt]);
                    mma16816(acc[mt][nt], ah[mt], bl[nt]);
                    mma16816(acc[mt][nt], al[mt], bh[nt]);
                }
        }
        __syncthreads();
    }

    const int r_base = row0 + wm * 32 + (lane >> 2);
    const int c_base = n0 + wn * 32 + (lane & 3) * 2;
#pragma unroll
    for (int mt = 0; mt < 2; mt++)
#pragma unroll
        for (int half = 0; half < 2; half++) {
            int r = r_base + mt * 16 + half * 8;
            if (r >= N_NODES) continue;
#pragma unroll
            for (int nt = 0; nt < 4; nt++) {
                int cc = c_base + nt * 8;
                float v0 = acc[mt][nt][half * 2 + 0] + bias[cc];
                float v1 = acc[mt][nt][half * 2 + 1] + bias[cc + 1];
                if (do_relu) { v0 = fmaxf(v0, 0.f); v1 = fmaxf(v1, 0.f); }
                if (outf) *(float2*)&outf[(size_t)r * ldc + cc] = make_float2(v0, v1);
                if (outh) {
                    __half2 o = __floats2half2_rn(v0, v1);
                    *(uint32_t*)&outh[(size_t)r * ldc + cc] = *(uint32_t*)&o;
                }
            }
        }
}

// ---------------- log_softmax ----------------
__global__ void logsoftmax_kernel(float* __restrict__ logits) {
    const int lane = threadIdx.x & 31;
    const int wid = threadIdx.x >> 5;
    const int row = blockIdx.x * (blockDim.x >> 5) + wid;
    if (row >= N_NODES) return;
    float* p = logits + (size_t)row * NCLS;
    float v0 = p[lane];
    float v1 = p[lane + 32];
    float m = fmaxf(v0, v1);
#pragma unroll
    for (int off = 16; off > 0; off >>= 1)
        m = fmaxf(m, __shfl_xor_sync(0xffffffffu, m, off));
    float s = expf(v0 - m) + expf(v1 - m);
#pragma unroll
    for (int off = 16; off > 0; off >>= 1)
        s += __shfl_xor_sync(0xffffffffu, s, off);
    float lse = m + logf(s);
    p[lane] = v0 - lse;
    p[lane + 32] = v1 - lse;
}

// ---------------- launch ----------------
extern "C" void kernel_launch(void* const* d_in, const int* in_sizes, int n_in,
                              void* d_out, int out_size) {
    const float* x        = (const float*)d_in[0];
    const float* edge_val = (const float*)d_in[1];
    const float* W_in     = (const float*)d_in[2];
    const float* b_in     = (const float*)d_in[3];
    const float* conv_W   = (const float*)d_in[4];
    const float* W_out    = (const float*)d_in[5];
    const float* b_out    = (const float*)d_in[6];
    const int*   edge_row = (const int*)d_in[7];
    const int*   edge_col = (const int*)d_in[8];
    float* out = (float*)d_out;

    float *x0_ptr;
    __half *hfA, *hfB;
    __nv_bfloat16 *xhi, *xlo, *mhi, *mlo, *winh, *winl, *wlh, *wll, *woh, *wol;
    cudaGetSymbolAddress((void**)&hfA, g_hfA);
    cudaGetSymbolAddress((void**)&hfB, g_hfB);
    cudaGetSymbolAddress((void**)&x0_ptr, g_x0);
    cudaGetSymbolAddress((void**)&xhi, g_xhi);
    cudaGetSymbolAddress((void**)&xlo, g_xlo);
    cudaGetSymbolAddress((void**)&mhi, g_mhi);
    cudaGetSymbolAddress((void**)&mlo, g_mlo);
    cudaGetSymbolAddress((void**)&winh, g_Winhi);
    cudaGetSymbolAddress((void**)&winl, g_Winlo);
    cudaGetSymbolAddress((void**)&wlh, g_Wlhi);
    cudaGetSymbolAddress((void**)&wll, g_Wllo);
    cudaGetSymbolAddress((void**)&woh, g_Wouthi);
    cudaGetSymbolAddress((void**)&wol, g_Woutlo);

    int nsm = 148;
    cudaDeviceGetAttribute(&nsm, cudaDevAttrMultiProcessorCount, 0);

    cudaFuncSetAttribute(mma_gemm_kernel, cudaFuncAttributeMaxDynamicSharedMemorySize, GEMM_SMEM);
    cudaFuncSetAttribute(fused_layer_kernel, cudaFuncAttributeMaxDynamicSharedMemorySize, FUSED_SMEM);

    // 1. CSR build + precision splits
    zero_cnt_kernel<<<(N_NODES + 255) / 256, 256>>>();
    count_kernel<<<(N_EDGES + 255) / 256, 256>>>(edge_row);
    scan_kernel<<<1, 1024>>>();
    scatter_kernel<<<(N_EDGES + 255) / 256, 256>>>(edge_row, edge_col, edge_val);
    split_x_kernel<<<(int)(((size_t)N_NODES * F_IN / 4 + 255) / 256), 256>>>(x);
    {
        int total = HID * F_IN + NLAYERS * HID * HID + NCLS * HID;
        conv_weights_kernel<<<(total + 255) / 256, 256>>>(W_in, conv_W, W_out);
    }

    // 2. input GEMM: hA(fp16, scale 1) = x0(fp32) = relu(x @ W_in + b_in)
    {
        dim3 grid(HID / BN, (N_NODES + BM - 1) / BM);
        mma_gemm_kernel<<<grid, 256, GEMM_SMEM>>>(
            xhi, xlo, F_IN, F_IN / BKC, winh, winl, b_in, x0_ptr, hfA, HID, 1);
    }

    // 3. warp-specialized fused GCN2 layers (ping-pong scaled fp16 h buffers)
    {
        __half* bufs[2] = {hfA, hfB};
        double sc = 1.0;
        for (int l = 0; l < NLAYERS; l++) {
            float beta = (float)log(0.5 / (double)(l + 1) + 1.0);
            float unscale = (float)sc;
            float scale_out = (float)(1.0 / (sc * 16.0));
            fused_layer_kernel<<<nsm, 512, FUSED_SMEM>>>(
                bufs[l & 1], bufs[(l + 1) & 1],
                wlh + (size_t)l * HID * HID, wll + (size_t)l * HID * HID,
                beta, unscale, scale_out, l == NLAYERS - 1);
            sc *= 16.0;
        }
    }

    // 4. output GEMM (MMA, bf16x3): logits = h @ W_out + b_out
    {
        dim3 grid(1, (N_NODES + BM - 1) / BM);
        mma_gemm_kernel<<<grid, 256, GEMM_SMEM>>>(
            mhi, mlo, HID, HID / BKC, woh, wol, b_out, out, nullptr, NCLS, 0);
    }

    // 5. log_softmax in place
    logsoftmax_kernel<<<(N_NODES + 7) / 8, 256>>>(out);
}